// round 7
// baseline (speedup 1.0000x reference)
#include <cuda_runtime.h>

#define BB 4
#define NN 8192
#define CC 64
#define OUTD 64
#define KNNK 36
#define BN (BB*NN)
#define KBLK 128
#define NSPLIT 2
#define HALF (NN/NSPLIT)       // 4096 candidates per split
#define TILE 256
#define SAMPLE 512             // phase-A sample size
#define PKEEP 12               // phase-A top-K (threshold = 12th smallest)
#define CAP 224                // survivor capacity per thread

// Device scratch (allocation-free rule: __device__ globals)
__device__ float4 g_xyz4[BN];             // (sq, x, y, z) packed per point
__device__ float  g_vfeat[BN*OUTD];       // relu([feature,xyz] @ W_v + b_v)
__device__ int    g_knn[BN*KNNK];         // final top-36 neighbor indices
__device__ float  g_pd[NSPLIT*BN*KNNK];   // partial top-36 distances
__device__ int    g_pi[NSPLIT*BN*KNNK];   // partial top-36 indices
__device__ unsigned char g_fail[NSPLIT*BN]; // per (q,half) fallback flag

// ---------------------------------------------------------------------------
__global__ void pack_xyz_kernel(const float* __restrict__ xyz) {
    int i = blockIdx.x * blockDim.x + threadIdx.x;
    if (i >= BN) return;
    float x = xyz[3*i], y = xyz[3*i+1], z = xyz[3*i+2];
    g_xyz4[i] = make_float4(x*x + y*y + z*z, x, y, z);
}

// ---------------------------------------------------------------------------
// v_feat = relu(concat([feature, xyz]) @ W_v + b_v)   (B,N,64)
// ---------------------------------------------------------------------------
__global__ __launch_bounds__(256) void vfeat_kernel(
    const float* __restrict__ feature,
    const float* __restrict__ xyz,
    const float* __restrict__ Wv,
    const float* __restrict__ bv)
{
    __shared__ float fsh[4][68];
    int sub = threadIdx.x >> 6;
    int t   = threadIdx.x & 63;
    int p   = blockIdx.x * 4 + sub;
    fsh[sub][t] = feature[p*64 + t];
    if (t < 3) fsh[sub][64 + t] = xyz[p*3 + t];
    __syncthreads();
    const float* f = fsh[sub];
    float acc = bv[t];
    #pragma unroll
    for (int c = 0; c < 67; c++)
        acc = fmaf(f[c], Wv[c*64 + t], acc);
    g_vfeat[p*64 + t] = fmaxf(acc, 0.0f);
}

// ---------------------------------------------------------------------------
// Equality-replace insert into a 36-entry register list.
// ---------------------------------------------------------------------------
__device__ __forceinline__ void topk_insert_eq(
    float d, int idx, float* kd, int* ki, float& worst)
{
    #pragma unroll
    for (int s = 0; s < KNNK; s++) {
        bool h = (kd[s] == worst);
        kd[s] = h ? d   : kd[s];
        ki[s] = h ? idx : ki[s];
    }
    float w = kd[0];
    #pragma unroll
    for (int s = 1; s < KNNK; s++)
        w = fmaxf(w, kd[s]);
    worst = w;
}

// ---------------------------------------------------------------------------
// KNN via threshold + collect (exact with fallback flag).
// Phase A: top-12 distances of first SAMPLE candidates -> threshold T.
// Phase B: collect all candidates with d < T (fixed threshold, chain-free
//          bitmask scan) into per-thread local-memory survivor arrays.
// Phase C: exact top-36 among survivors; fail -> flag for fallback kernel.
// ---------------------------------------------------------------------------
__global__ __launch_bounds__(KBLK) void knn_select_kernel() {
    __shared__ float4 tile[TILE];
    const unsigned FULL = 0xffffffffu;

    int tid = threadIdx.x;
    int q = blockIdx.x * KBLK + tid;
    int h = blockIdx.y;
    int b = q >> 13;

    float4 me = g_xyz4[q];
    float nx = -2.0f * me.y, ny = -2.0f * me.z, nz = -2.0f * me.w;

    const float4* __restrict__ cand = g_xyz4 + b * NN + h * HALF;
    const int idx_off = h * HALF;

    // ---------------- Phase A: threshold from first SAMPLE candidates -------
    float pd[PKEEP];
    float worstA;
    for (int base = 0; base < SAMPLE; base += TILE) {
        __syncthreads();
        tile[tid]        = cand[base + tid];
        tile[tid + KBLK] = cand[base + tid + KBLK];
        __syncthreads();

        if (base == 0) {
            #pragma unroll
            for (int s = 0; s < PKEEP; s++) {
                float4 c = tile[s];
                float d = fmaf(nx, c.y, c.x);
                d = fmaf(ny, c.z, d); d = fmaf(nz, c.w, d);
                pd[s] = d;
            }
            float w = pd[0];
            #pragma unroll
            for (int s = 1; s < PKEEP; s++) w = fmaxf(w, pd[s]);
            worstA = w;
        }

        for (int js = 0; js < TILE; js += 32) {
            unsigned m0 = 0, m1 = 0;
            #pragma unroll
            for (int jj = 0; jj < 16; jj++) {
                float4 c = tile[js + jj];
                float d = fmaf(nx, c.y, c.x);
                d = fmaf(ny, c.z, d); d = fmaf(nz, c.w, d);
                m0 |= (d < worstA) ? (1u << jj) : 0u;
            }
            #pragma unroll
            for (int jj = 16; jj < 32; jj++) {
                float4 c = tile[js + jj];
                float d = fmaf(nx, c.y, c.x);
                d = fmaf(ny, c.z, d); d = fmaf(nz, c.w, d);
                m1 |= (d < worstA) ? (1u << jj) : 0u;
            }
            unsigned mask = m0 | m1;
            if (base == 0 && js == 0) mask &= 0xFFFFF000u;  // first 12 filled

            if (__any_sync(FULL, mask != 0u)) {
                while (mask) {
                    int jj = __ffs(mask) - 1;
                    mask &= mask - 1;
                    float4 c = tile[js + jj];
                    float d = fmaf(nx, c.y, c.x);
                    d = fmaf(ny, c.z, d); d = fmaf(nz, c.w, d);
                    if (d < worstA) {
                        #pragma unroll
                        for (int s = 0; s < PKEEP; s++) {
                            bool hh = (pd[s] == worstA);
                            pd[s] = hh ? d : pd[s];
                        }
                        float w = pd[0];
                        #pragma unroll
                        for (int s = 1; s < PKEEP; s++) w = fmaxf(w, pd[s]);
                        worstA = w;
                    }
                }
            }
        }
    }
    const float T = worstA;   // fixed threshold for phase B

    // ---------------- Phase B: collect survivors (d < T) --------------------
    float sd[CAP];
    int   si[CAP];
    int cnt = 0;

    for (int base = 0; base < HALF; base += TILE) {
        __syncthreads();
        tile[tid]        = cand[base + tid];
        tile[tid + KBLK] = cand[base + tid + KBLK];
        __syncthreads();

        for (int js = 0; js < TILE; js += 32) {
            unsigned m0 = 0, m1 = 0, m2 = 0, m3 = 0;
            #pragma unroll
            for (int jj = 0; jj < 8; jj++) {
                float4 c = tile[js + jj];
                float d = fmaf(nx, c.y, c.x);
                d = fmaf(ny, c.z, d); d = fmaf(nz, c.w, d);
                m0 |= (d < T) ? (1u << jj) : 0u;
            }
            #pragma unroll
            for (int jj = 8; jj < 16; jj++) {
                float4 c = tile[js + jj];
                float d = fmaf(nx, c.y, c.x);
                d = fmaf(ny, c.z, d); d = fmaf(nz, c.w, d);
                m1 |= (d < T) ? (1u << jj) : 0u;
            }
            #pragma unroll
            for (int jj = 16; jj < 24; jj++) {
                float4 c = tile[js + jj];
                float d = fmaf(nx, c.y, c.x);
                d = fmaf(ny, c.z, d); d = fmaf(nz, c.w, d);
                m2 |= (d < T) ? (1u << jj) : 0u;
            }
            #pragma unroll
            for (int jj = 24; jj < 32; jj++) {
                float4 c = tile[js + jj];
                float d = fmaf(nx, c.y, c.x);
                d = fmaf(ny, c.z, d); d = fmaf(nz, c.w, d);
                m3 |= (d < T) ? (1u << jj) : 0u;
            }
            unsigned mask = (m0 | m1) | (m2 | m3);
            if (__any_sync(FULL, mask != 0u)) {
                while (mask) {
                    int jj = __ffs(mask) - 1;
                    mask &= mask - 1;
                    float4 c = tile[js + jj];
                    float d = fmaf(nx, c.y, c.x);
                    d = fmaf(ny, c.z, d); d = fmaf(nz, c.w, d);
                    if (cnt < CAP) { sd[cnt] = d; si[cnt] = idx_off + base + js + jj; }
                    cnt++;
                }
            }
        }
    }

    // ---------------- Phase C: exact top-36 among survivors -----------------
    bool fail = (cnt < KNNK) || (cnt > CAP);
    g_fail[(size_t)h * BN + q] = fail ? 1 : 0;

    if (!fail) {
        float kd[KNNK];
        int   ki[KNNK];
        #pragma unroll
        for (int s = 0; s < KNNK; s++) { kd[s] = sd[s]; ki[s] = si[s]; }
        float worst = kd[0];
        #pragma unroll
        for (int s = 1; s < KNNK; s++) worst = fmaxf(worst, kd[s]);

        for (int it = KNNK; it < cnt; it++) {
            float d = sd[it];
            if (d < worst)
                topk_insert_eq(d, si[it], kd, ki, worst);
        }

        size_t o = ((size_t)h * BN + q) * KNNK;
        #pragma unroll
        for (int s = 0; s < KNNK; s++) {
            g_pd[o + s] = kd[s];
            g_pi[o + s] = ki[s];
        }
    }
}

// ---------------------------------------------------------------------------
// Fallback: exact streaming top-36 for flagged (q,half) pairs (rare).
// Direct LDG (xyz4 is L1/L2 resident); unflagged threads exit immediately.
// ---------------------------------------------------------------------------
__global__ __launch_bounds__(KBLK) void knn_fallback_kernel() {
    int tid = threadIdx.x;
    int q = blockIdx.x * KBLK + tid;
    int h = blockIdx.y;
    if (!g_fail[(size_t)h * BN + q]) return;

    int b = q >> 13;
    float4 me = g_xyz4[q];
    float nx = -2.0f * me.y, ny = -2.0f * me.z, nz = -2.0f * me.w;
    const float4* __restrict__ cand = g_xyz4 + b * NN + h * HALF;
    const int idx_off = h * HALF;

    float kd[KNNK];
    int   ki[KNNK];
    #pragma unroll
    for (int s = 0; s < KNNK; s++) {
        float4 c = __ldg(cand + s);
        float d = fmaf(nx, c.y, c.x);
        d = fmaf(ny, c.z, d); d = fmaf(nz, c.w, d);
        kd[s] = d; ki[s] = idx_off + s;
    }
    float worst = kd[0];
    #pragma unroll
    for (int s = 1; s < KNNK; s++) worst = fmaxf(worst, kd[s]);

    for (int j = KNNK; j < HALF; j++) {
        float4 c = __ldg(cand + j);
        float d = fmaf(nx, c.y, c.x);
        d = fmaf(ny, c.z, d); d = fmaf(nz, c.w, d);
        if (d < worst)
            topk_insert_eq(d, idx_off + j, kd, ki, worst);
    }

    size_t o = ((size_t)h * BN + q) * KNNK;
    #pragma unroll
    for (int s = 0; s < KNNK; s++) {
        g_pd[o + s] = kd[s];
        g_pi[o + s] = ki[s];
    }
}

// ---------------------------------------------------------------------------
// Merge: per query, exact top-36 of the union of the 2 partial top-36s.
// ---------------------------------------------------------------------------
__global__ __launch_bounds__(KBLK) void knn_merge_kernel() {
    int q = blockIdx.x * KBLK + threadIdx.x;

    float kd[KNNK];
    int   ki[KNNK];
    size_t o0 = (size_t)q * KNNK;
    #pragma unroll
    for (int s = 0; s < KNNK; s++) { kd[s] = g_pd[o0 + s]; ki[s] = g_pi[o0 + s]; }
    float worst = kd[0];
    #pragma unroll
    for (int s = 1; s < KNNK; s++)
        worst = fmaxf(worst, kd[s]);

    size_t o1 = ((size_t)BN + q) * KNNK;
    #pragma unroll
    for (int it = 0; it < KNNK; it++) {
        float d = g_pd[o1 + it];
        if (d < worst)
            topk_insert_eq(d, g_pi[o1 + it], kd, ki, worst);
    }

    #pragma unroll
    for (int s = 0; s < KNNK; s++)
        g_knn[(size_t)q * KNNK + s] = ki[s];
}

// ---------------------------------------------------------------------------
// Attention + suffix GEMM (coalesced row reads + shuffle reduce).
// ---------------------------------------------------------------------------
__global__ __launch_bounds__(256) void attn_kernel(
    const float* __restrict__ feature,
    const float* __restrict__ Wsuf,
    const float* __restrict__ bsuf,
    float* __restrict__ out)
{
    __shared__ float osh[8][64];
    const unsigned FULL = 0xffffffffu;
    int w    = threadIdx.x >> 5;
    int lane = threadIdx.x & 31;
    int p    = blockIdx.x * 8 + w;
    int b    = p >> 13;

    const float* frow = feature + (size_t)p * 64;
    float2 q2 = *(const float2*)(frow + 2*lane);

    int idxA = g_knn[p*KNNK + lane];
    int idxB = (lane < 4) ? g_knn[p*KNNK + 32 + lane] : 0;

    const float* fbase = feature + (size_t)b * NN * 64;
    float wA = 0.0f, wB = -3.4e38f;

    #pragma unroll
    for (int k = 0; k < KNNK; k++) {
        int j = (k < 32) ? __shfl_sync(FULL, idxA, k)
                         : __shfl_sync(FULL, idxB, k - 32);
        float2 f2 = *(const float2*)(fbase + (size_t)j * 64 + 2*lane);
        float part = fmaf(f2.x, q2.x, f2.y * q2.y);
        #pragma unroll
        for (int s = 16; s; s >>= 1)
            part += __shfl_xor_sync(FULL, part, s);
        if (k < 32) { if (lane == k)      wA = part; }
        else        { if (lane == k - 32) wB = part; }
    }

    float m = fmaxf(wA, (lane < 4) ? wB : -3.4e38f);
    #pragma unroll
    for (int s = 16; s; s >>= 1)
        m = fmaxf(m, __shfl_xor_sync(FULL, m, s));
    float eA = __expf(wA - m);
    float eB = (lane < 4) ? __expf(wB - m) : 0.0f;
    float ssum = eA + eB;
    #pragma unroll
    for (int s = 16; s; s >>= 1)
        ssum += __shfl_xor_sync(FULL, ssum, s);
    float inv = 1.0f / ssum;
    eA *= inv; eB *= inv;

    const float* vbase = g_vfeat + (size_t)b * NN * 64;
    float ox = 0.0f, oy = 0.0f;
    #pragma unroll
    for (int k = 0; k < KNNK; k++) {
        int j; float wk;
        if (k < 32) { j = __shfl_sync(FULL, idxA, k);      wk = __shfl_sync(FULL, eA, k); }
        else        { j = __shfl_sync(FULL, idxB, k - 32); wk = __shfl_sync(FULL, eB, k - 32); }
        float2 v2 = *(const float2*)(vbase + (size_t)j * 64 + 2*lane);
        ox = fmaf(wk, v2.x, ox);
        oy = fmaf(wk, v2.y, oy);
    }

    osh[w][2*lane]     = ox;
    osh[w][2*lane + 1] = oy;
    __syncwarp();
    float2 acc = *(const float2*)(bsuf + 2*lane);
    #pragma unroll 8
    for (int c = 0; c < 64; c++) {
        float oc = osh[w][c];
        float2 wv = *(const float2*)(Wsuf + c*64 + 2*lane);
        acc.x = fmaf(oc, wv.x, acc.x);
        acc.y = fmaf(oc, wv.y, acc.y);
    }
    *(float2*)(out + (size_t)p * 64 + 2*lane) = acc;
}

__global__ void tail_kernel(float* __restrict__ out, int out_size) {
    int i = BN*OUTD + blockIdx.x * blockDim.x + threadIdx.x;
    if (i < out_size) out[i] = (float)NN;
}

extern "C" void kernel_launch(void* const* d_in, const int* in_sizes, int n_in,
                              void* d_out, int out_size) {
    const float* feature = (const float*)d_in[0];
    const float* xyz     = (const float*)d_in[1];
    const float* Wv      = (const float*)d_in[2];
    const float* bv      = (const float*)d_in[3];
    const float* Wsuf    = (const float*)d_in[4];
    const float* bsuf    = (const float*)d_in[5];
    float* out = (float*)d_out;

    pack_xyz_kernel<<<(BN + 255) / 256, 256>>>(xyz);
    vfeat_kernel<<<BN / 4, 256>>>(feature, xyz, Wv, bv);
    dim3 kgrid(BN / KBLK, NSPLIT);
    knn_select_kernel<<<kgrid, KBLK>>>();
    knn_fallback_kernel<<<kgrid, KBLK>>>();
    knn_merge_kernel<<<BN / KBLK, KBLK>>>();
    attn_kernel<<<BN / 8, 256>>>(feature, Wsuf, bsuf, out);

    if (out_size > BN*OUTD) {
        int extra = out_size - BN*OUTD;
        tail_kernel<<<(extra + 255) / 256, 256>>>(out, out_size);
    }
}

// round 8
// speedup vs baseline: 1.4996x; 1.4996x over previous
#include <cuda_runtime.h>

#define BB 4
#define NN 8192
#define CC 64
#define OUTD 64
#define KNNK 36
#define BN (BB*NN)
#define KBLK 128
#define NSPLIT 2
#define HALF (NN/NSPLIT)       // 4096 candidates per split
#define TILE 256
#define SAMPLE 512             // phase-A sample size
#define PKEEP 28               // phase-A top-K (threshold = 28th smallest)
#define CAP 416                // survivor capacity per thread

// Device scratch (allocation-free rule: __device__ globals)
__device__ float4 g_xyz4[BN];             // (sq, x, y, z) packed per point
__device__ float  g_vfeat[BN*OUTD];       // relu([feature,xyz] @ W_v + b_v)
__device__ float  g_pd[NSPLIT*BN*KNNK];   // partial top-36 distances
__device__ int    g_pi[NSPLIT*BN*KNNK];   // partial top-36 indices
__device__ unsigned char g_fail[NSPLIT*BN]; // per (q,half) fallback flag

// ---------------------------------------------------------------------------
__global__ void pack_xyz_kernel(const float* __restrict__ xyz) {
    int i = blockIdx.x * blockDim.x + threadIdx.x;
    if (i >= BN) return;
    float x = xyz[3*i], y = xyz[3*i+1], z = xyz[3*i+2];
    g_xyz4[i] = make_float4(x*x + y*y + z*z, x, y, z);
}

// ---------------------------------------------------------------------------
// v_feat = relu(concat([feature, xyz]) @ W_v + b_v)   (B,N,64)
// ---------------------------------------------------------------------------
__global__ __launch_bounds__(256) void vfeat_kernel(
    const float* __restrict__ feature,
    const float* __restrict__ xyz,
    const float* __restrict__ Wv,
    const float* __restrict__ bv)
{
    __shared__ float fsh[4][68];
    int sub = threadIdx.x >> 6;
    int t   = threadIdx.x & 63;
    int p   = blockIdx.x * 4 + sub;
    fsh[sub][t] = feature[p*64 + t];
    if (t < 3) fsh[sub][64 + t] = xyz[p*3 + t];
    __syncthreads();
    const float* f = fsh[sub];
    float acc = bv[t];
    #pragma unroll
    for (int c = 0; c < 67; c++)
        acc = fmaf(f[c], Wv[c*64 + t], acc);
    g_vfeat[p*64 + t] = fmaxf(acc, 0.0f);
}

// ---------------------------------------------------------------------------
// Equality-replace insert into a 36-entry register list.
// ---------------------------------------------------------------------------
__device__ __forceinline__ void topk_insert_eq(
    float d, int idx, float* kd, int* ki, float& worst)
{
    #pragma unroll
    for (int s = 0; s < KNNK; s++) {
        bool h = (kd[s] == worst);
        kd[s] = h ? d   : kd[s];
        ki[s] = h ? idx : ki[s];
    }
    float w = kd[0];
    #pragma unroll
    for (int s = 1; s < KNNK; s++)
        w = fmaxf(w, kd[s]);
    worst = w;
}

// ---------------------------------------------------------------------------
// KNN via threshold + collect (exact with fallback flag).
// Phase A: top-28 distances of first SAMPLE candidates -> threshold T.
// Phase B: collect all candidates with d <= T (fixed threshold, chain-free
//          bitmask scan) into per-thread local-memory survivor arrays.
// Phase C: exact top-36 among survivors; fail -> flag for fallback kernel.
// Exactness: if cnt >= 36 (with <=), the half's top-36 all satisfy d <= T,
// so they are among the survivors. cnt outside [36, CAP] -> flagged.
// ---------------------------------------------------------------------------
__global__ __launch_bounds__(KBLK) void knn_select_kernel() {
    __shared__ float4 tile[TILE];
    const unsigned FULL = 0xffffffffu;

    int tid = threadIdx.x;
    int q = blockIdx.x * KBLK + tid;
    int h = blockIdx.y;
    int b = q >> 13;

    float4 me = g_xyz4[q];
    float nx = -2.0f * me.y, ny = -2.0f * me.z, nz = -2.0f * me.w;

    const float4* __restrict__ cand = g_xyz4 + b * NN + h * HALF;
    const int idx_off = h * HALF;

    // ---------------- Phase A: threshold = 28th smallest of first 512 -------
    float pd[PKEEP];
    float worstA;
    for (int base = 0; base < SAMPLE; base += TILE) {
        __syncthreads();
        tile[tid]        = cand[base + tid];
        tile[tid + KBLK] = cand[base + tid + KBLK];
        __syncthreads();

        if (base == 0) {
            #pragma unroll
            for (int s = 0; s < PKEEP; s++) {
                float4 c = tile[s];
                float d = fmaf(nx, c.y, c.x);
                d = fmaf(ny, c.z, d); d = fmaf(nz, c.w, d);
                pd[s] = d;
            }
            float w = pd[0];
            #pragma unroll
            for (int s = 1; s < PKEEP; s++) w = fmaxf(w, pd[s]);
            worstA = w;
        }

        for (int js = 0; js < TILE; js += 32) {
            unsigned m0 = 0, m1 = 0;
            #pragma unroll
            for (int jj = 0; jj < 16; jj++) {
                float4 c = tile[js + jj];
                float d = fmaf(nx, c.y, c.x);
                d = fmaf(ny, c.z, d); d = fmaf(nz, c.w, d);
                m0 |= (d < worstA) ? (1u << jj) : 0u;
            }
            #pragma unroll
            for (int jj = 16; jj < 32; jj++) {
                float4 c = tile[js + jj];
                float d = fmaf(nx, c.y, c.x);
                d = fmaf(ny, c.z, d); d = fmaf(nz, c.w, d);
                m1 |= (d < worstA) ? (1u << jj) : 0u;
            }
            unsigned mask = m0 | m1;
            if (base == 0 && js == 0) mask &= 0xF0000000u;  // first 28 filled

            if (__any_sync(FULL, mask != 0u)) {
                while (mask) {
                    int jj = __ffs(mask) - 1;
                    mask &= mask - 1;
                    float4 c = tile[js + jj];
                    float d = fmaf(nx, c.y, c.x);
                    d = fmaf(ny, c.z, d); d = fmaf(nz, c.w, d);
                    if (d < worstA) {
                        #pragma unroll
                        for (int s = 0; s < PKEEP; s++) {
                            bool hh = (pd[s] == worstA);
                            pd[s] = hh ? d : pd[s];
                        }
                        float w = pd[0];
                        #pragma unroll
                        for (int s = 1; s < PKEEP; s++) w = fmaxf(w, pd[s]);
                        worstA = w;
                    }
                }
            }
        }
    }
    const float T = worstA;   // fixed threshold for phase B

    // ---------------- Phase B: collect survivors (d <= T) -------------------
    float sd[CAP];
    int   si[CAP];
    int cnt = 0;

    for (int base = 0; base < HALF; base += TILE) {
        __syncthreads();
        tile[tid]        = cand[base + tid];
        tile[tid + KBLK] = cand[base + tid + KBLK];
        __syncthreads();

        for (int js = 0; js < TILE; js += 32) {
            unsigned m0 = 0, m1 = 0, m2 = 0, m3 = 0;
            #pragma unroll
            for (int jj = 0; jj < 8; jj++) {
                float4 c = tile[js + jj];
                float d = fmaf(nx, c.y, c.x);
                d = fmaf(ny, c.z, d); d = fmaf(nz, c.w, d);
                m0 |= (d <= T) ? (1u << jj) : 0u;
            }
            #pragma unroll
            for (int jj = 8; jj < 16; jj++) {
                float4 c = tile[js + jj];
                float d = fmaf(nx, c.y, c.x);
                d = fmaf(ny, c.z, d); d = fmaf(nz, c.w, d);
                m1 |= (d <= T) ? (1u << jj) : 0u;
            }
            #pragma unroll
            for (int jj = 16; jj < 24; jj++) {
                float4 c = tile[js + jj];
                float d = fmaf(nx, c.y, c.x);
                d = fmaf(ny, c.z, d); d = fmaf(nz, c.w, d);
                m2 |= (d <= T) ? (1u << jj) : 0u;
            }
            #pragma unroll
            for (int jj = 24; jj < 32; jj++) {
                float4 c = tile[js + jj];
                float d = fmaf(nx, c.y, c.x);
                d = fmaf(ny, c.z, d); d = fmaf(nz, c.w, d);
                m3 |= (d <= T) ? (1u << jj) : 0u;
            }
            unsigned mask = (m0 | m1) | (m2 | m3);
            if (__any_sync(FULL, mask != 0u)) {
                while (mask) {
                    int jj = __ffs(mask) - 1;
                    mask &= mask - 1;
                    float4 c = tile[js + jj];
                    float d = fmaf(nx, c.y, c.x);
                    d = fmaf(ny, c.z, d); d = fmaf(nz, c.w, d);
                    if (cnt < CAP) { sd[cnt] = d; si[cnt] = idx_off + base + js + jj; }
                    cnt++;
                }
            }
        }
    }

    // ---------------- Phase C: exact top-36 among survivors -----------------
    bool fail = (cnt < KNNK) || (cnt > CAP);
    g_fail[(size_t)h * BN + q] = fail ? 1 : 0;

    if (!fail) {
        float kd[KNNK];
        int   ki[KNNK];
        #pragma unroll
        for (int s = 0; s < KNNK; s++) { kd[s] = sd[s]; ki[s] = si[s]; }
        float worst = kd[0];
        #pragma unroll
        for (int s = 1; s < KNNK; s++) worst = fmaxf(worst, kd[s]);

        for (int it = KNNK; it < cnt; it++) {
            float d = sd[it];
            if (d < worst)
                topk_insert_eq(d, si[it], kd, ki, worst);
        }

        size_t o = ((size_t)h * BN + q) * KNNK;
        #pragma unroll
        for (int s = 0; s < KNNK; s++) {
            g_pd[o + s] = kd[s];
            g_pi[o + s] = ki[s];
        }
    }
}

// ---------------------------------------------------------------------------
// Fallback: exact streaming top-36 for flagged (q,half) pairs (expected ~0).
// ---------------------------------------------------------------------------
__global__ __launch_bounds__(KBLK) void knn_fallback_kernel() {
    int tid = threadIdx.x;
    int q = blockIdx.x * KBLK + tid;
    int h = blockIdx.y;
    if (!g_fail[(size_t)h * BN + q]) return;

    int b = q >> 13;
    float4 me = g_xyz4[q];
    float nx = -2.0f * me.y, ny = -2.0f * me.z, nz = -2.0f * me.w;
    const float4* __restrict__ cand = g_xyz4 + b * NN + h * HALF;
    const int idx_off = h * HALF;

    float kd[KNNK];
    int   ki[KNNK];
    #pragma unroll
    for (int s = 0; s < KNNK; s++) {
        float4 c = __ldg(cand + s);
        float d = fmaf(nx, c.y, c.x);
        d = fmaf(ny, c.z, d); d = fmaf(nz, c.w, d);
        kd[s] = d; ki[s] = idx_off + s;
    }
    float worst = kd[0];
    #pragma unroll
    for (int s = 1; s < KNNK; s++) worst = fmaxf(worst, kd[s]);

    for (int j = KNNK; j < HALF; j++) {
        float4 c = __ldg(cand + j);
        float d = fmaf(nx, c.y, c.x);
        d = fmaf(ny, c.z, d); d = fmaf(nz, c.w, d);
        if (d < worst)
            topk_insert_eq(d, idx_off + j, kd, ki, worst);
    }

    size_t o = ((size_t)h * BN + q) * KNNK;
    #pragma unroll
    for (int s = 0; s < KNNK; s++) {
        g_pd[o + s] = kd[s];
        g_pi[o + s] = ki[s];
    }
}

// ---------------------------------------------------------------------------
// Order-preserving float -> uint map for bit-bisection selection.
// ---------------------------------------------------------------------------
__device__ __forceinline__ unsigned f2mono(float f) {
    unsigned u = __float_as_uint(f);
    return (u & 0x80000000u) ? ~u : (u | 0x80000000u);
}

// ---------------------------------------------------------------------------
// Fused merge + attention + suffix GEMM. Warp per point.
// Merge: exact top-36 of the 72 (=2x36) partial candidates via warp ballot
// bit-bisection (find 36th-smallest value V, 32 iters), then ballot-prefix
// compaction of the <=V set into 36 smem slots. Order is irrelevant for
// softmax attention (permutation invariant).
// ---------------------------------------------------------------------------
__global__ __launch_bounds__(256) void attn_kernel(
    const float* __restrict__ feature,
    const float* __restrict__ Wsuf,
    const float* __restrict__ bsuf,
    float* __restrict__ out)
{
    __shared__ int   ish[8][40];
    __shared__ float osh[8][64];
    const unsigned FULL = 0xffffffffu;
    int w    = threadIdx.x >> 5;
    int lane = threadIdx.x & 31;
    int p    = blockIdx.x * 8 + w;
    int b    = p >> 13;

    // ---- load the two partial top-36 lists (lanes 0..31 + lanes 0..3) ----
    size_t o0 = (size_t)p * KNNK;
    size_t o1 = (size_t)BN * KNNK + o0;
    unsigned uA0 = f2mono(g_pd[o0 + lane]);
    unsigned uA1 = f2mono(g_pd[o1 + lane]);
    unsigned uB0 = 0xFFFFFFFFu, uB1 = 0xFFFFFFFFu;
    int iA0 = g_pi[o0 + lane];
    int iA1 = g_pi[o1 + lane];
    int iB0 = 0, iB1 = 0;
    if (lane < 4) {
        uB0 = f2mono(g_pd[o0 + 32 + lane]);  iB0 = g_pi[o0 + 32 + lane];
        uB1 = f2mono(g_pd[o1 + 32 + lane]);  iB1 = g_pi[o1 + 32 + lane];
    }

    // ---- bit-bisection: V = 36th smallest of the 72 mono-uints ----
    unsigned prefix = 0;
    #pragma unroll
    for (int bit = 31; bit >= 0; bit--) {
        unsigned trial = prefix | ((1u << bit) - 1u);
        int cnt = __popc(__ballot_sync(FULL, uA0 <= trial))
                + __popc(__ballot_sync(FULL, uB0 <= trial) & 0xFu)
                + __popc(__ballot_sync(FULL, uA1 <= trial))
                + __popc(__ballot_sync(FULL, uB1 <= trial) & 0xFu);
        if (cnt < KNNK) prefix |= (1u << bit);
    }
    const unsigned V = prefix;

    // ---- compaction of the <=V set into slots 0..35 ----
    unsigned mA0 = __ballot_sync(FULL, uA0 <= V);
    unsigned mB0 = __ballot_sync(FULL, uB0 <= V) & 0xFu;
    unsigned mA1 = __ballot_sync(FULL, uA1 <= V);
    unsigned mB1 = __ballot_sync(FULL, uB1 <= V) & 0xFu;
    int baseB0 = __popc(mA0);
    int baseA1 = baseB0 + __popc(mB0);
    int baseB1 = baseA1 + __popc(mA1);
    unsigned lt = (1u << lane) - 1u;

    if ((uA0 <= V)) {
        int r = __popc(mA0 & lt);
        if (r < KNNK) ish[w][r] = iA0;
    }
    if (lane < 4 && (uB0 <= V)) {
        int r = baseB0 + __popc(mB0 & lt);
        if (r < KNNK) ish[w][r] = iB0;
    }
    if ((uA1 <= V)) {
        int r = baseA1 + __popc(mA1 & lt);
        if (r < KNNK) ish[w][r] = iA1;
    }
    if (lane < 4 && (uB1 <= V)) {
        int r = baseB1 + __popc(mB1 & lt);
        if (r < KNNK) ish[w][r] = iB1;
    }
    __syncwarp();

    int idxA = ish[w][lane];
    int idxB = (lane < 4) ? ish[w][32 + lane] : 0;

    // ---- attention logits (coalesced rows + shuffle reductions) ----
    const float* frow = feature + (size_t)p * 64;
    float2 q2 = *(const float2*)(frow + 2*lane);

    const float* fbase = feature + (size_t)b * NN * 64;
    float wA = 0.0f, wB = -3.4e38f;

    #pragma unroll
    for (int k = 0; k < KNNK; k++) {
        int j = (k < 32) ? __shfl_sync(FULL, idxA, k)
                         : __shfl_sync(FULL, idxB, k - 32);
        float2 f2 = *(const float2*)(fbase + (size_t)j * 64 + 2*lane);
        float part = fmaf(f2.x, q2.x, f2.y * q2.y);
        #pragma unroll
        for (int s = 16; s; s >>= 1)
            part += __shfl_xor_sync(FULL, part, s);
        if (k < 32) { if (lane == k)      wA = part; }
        else        { if (lane == k - 32) wB = part; }
    }

    float m = fmaxf(wA, (lane < 4) ? wB : -3.4e38f);
    #pragma unroll
    for (int s = 16; s; s >>= 1)
        m = fmaxf(m, __shfl_xor_sync(FULL, m, s));
    float eA = __expf(wA - m);
    float eB = (lane < 4) ? __expf(wB - m) : 0.0f;
    float ssum = eA + eB;
    #pragma unroll
    for (int s = 16; s; s >>= 1)
        ssum += __shfl_xor_sync(FULL, ssum, s);
    float inv = 1.0f / ssum;
    eA *= inv; eB *= inv;

    const float* vbase = g_vfeat + (size_t)b * NN * 64;
    float ox = 0.0f, oy = 0.0f;
    #pragma unroll
    for (int k = 0; k < KNNK; k++) {
        int j; float wk;
        if (k < 32) { j = __shfl_sync(FULL, idxA, k);      wk = __shfl_sync(FULL, eA, k); }
        else        { j = __shfl_sync(FULL, idxB, k - 32); wk = __shfl_sync(FULL, eB, k - 32); }
        float2 v2 = *(const float2*)(vbase + (size_t)j * 64 + 2*lane);
        ox = fmaf(wk, v2.x, ox);
        oy = fmaf(wk, v2.y, oy);
    }

    osh[w][2*lane]     = ox;
    osh[w][2*lane + 1] = oy;
    __syncwarp();
    float2 acc = *(const float2*)(bsuf + 2*lane);
    #pragma unroll 8
    for (int c = 0; c < 64; c++) {
        float oc = osh[w][c];
        float2 wv = *(const float2*)(Wsuf + c*64 + 2*lane);
        acc.x = fmaf(oc, wv.x, acc.x);
        acc.y = fmaf(oc, wv.y, acc.y);
    }
    *(float2*)(out + (size_t)p * 64 + 2*lane) = acc;
}

__global__ void tail_kernel(float* __restrict__ out, int out_size) {
    int i = BN*OUTD + blockIdx.x * blockDim.x + threadIdx.x;
    if (i < out_size) out[i] = (float)NN;
}

extern "C" void kernel_launch(void* const* d_in, const int* in_sizes, int n_in,
                              void* d_out, int out_size) {
    const float* feature = (const float*)d_in[0];
    const float* xyz     = (const float*)d_in[1];
    const float* Wv      = (const float*)d_in[2];
    const float* bv      = (const float*)d_in[3];
    const float* Wsuf    = (const float*)d_in[4];
    const float* bsuf    = (const float*)d_in[5];
    float* out = (float*)d_out;

    pack_xyz_kernel<<<(BN + 255) / 256, 256>>>(xyz);
    vfeat_kernel<<<BN / 4, 256>>>(feature, xyz, Wv, bv);
    dim3 kgrid(BN / KBLK, NSPLIT);
    knn_select_kernel<<<kgrid, KBLK>>>();
    knn_fallback_kernel<<<kgrid, KBLK>>>();
    attn_kernel<<<BN / 8, 256>>>(feature, Wsuf, bsuf, out);

    if (out_size > BN*OUTD) {
        int extra = out_size - BN*OUTD;
        tail_kernel<<<(extra + 255) / 256, 256>>>(out, out_size);
    }
}